// round 1
// baseline (speedup 1.0000x reference)
#include <cuda_runtime.h>
#include <cstdint>

// Problem constants (fixed shapes for this problem)
#define N_SESS   8192
#define N_TRIALS 1024
#define N_TILES  32          // 1024 / 32
#define MAIN_BLOCK 64        // 2 warps/block -> spread over SMs, <=1 warp per SMSP

// Packed masks, time-major: mask[tile*N_SESS + session]
__device__ unsigned g_cmask[N_TILES * N_SESS];
__device__ unsigned g_omask[N_TILES * N_SESS];

// ---------------------------------------------------------------------------
// Pack kernel: input (8192,1024,3) f32 -> 2 bitmasks per (session, 32-trial tile)
// One warp handles 32 consecutive trials of one session via ballot.
// ---------------------------------------------------------------------------
__global__ void pack_kernel(const float* __restrict__ in)
{
    int gtid   = blockIdx.x * blockDim.x + threadIdx.x;
    int warpId = gtid >> 5;            // [0, 8192*32)
    int lane   = gtid & 31;
    int s = warpId >> 5;               // session
    int w = warpId & 31;               // trial tile
    int t = w * 32 + lane;
    const float* p = in + (size_t)s * (N_TRIALS * 3) + (size_t)t * 3;
    float cl = p[0];
    float oc = p[2];
    unsigned mc = __ballot_sync(0xffffffffu, cl > 0.5f);
    unsigned mo = __ballot_sync(0xffffffffu, oc > 0.5f);
    if (lane == 0) {
        g_cmask[w * N_SESS + s] = mc;
        g_omask[w * N_SESS + s] = mo;
    }
}

// smooth_clamp(x, 0, 1), beta = 100.
// sp(z) = softplus(100 z)/100; result = x<0.5 ? sp(x) : 1 - sp(1-x)
// Symmetric: arg a = 0.5 - |x-0.5|. In base-2:
//   w = 144.269504*a ; sp = (max(w,0) + log2(1+2^(-|w|))) * (ln2/100)
__device__ __forceinline__ float smooth_clamp01(float x)
{
    float t = x - 0.5f;
    // w = 144.2695041*(0.5 - |t|)
    float w = fmaf(fabsf(t), -144.26950408889634f, 72.13475204444817f);
    float e = exp2f(-fabsf(w));
    float m = fmaxf(w, 0.0f);
    float l = __log2f(1.0f + e);
    float s = (m + l) * 0.006931471805599453f;
    return (x < 0.5f) ? s : 1.0f - s;
}

// ---------------------------------------------------------------------------
// Main scan kernel: one thread per session, 1024 serial steps.
// Output staged in shared tiles (32 steps) and flushed coalesced.
// ---------------------------------------------------------------------------
__global__ __launch_bounds__(MAIN_BLOCK, 1)
void agent_kernel(const float* __restrict__ a0,
                  const float* __restrict__ ga,
                  const float* __restrict__ gl,
                  const float* __restrict__ kv,
                  float2* __restrict__ out)
{
    const int tid   = blockIdx.x * blockDim.x + threadIdx.x;   // session
    const int lane  = threadIdx.x & 31;
    const int warp  = threadIdx.x >> 5;
    const int sbase = tid - lane;                               // warp's first session

    // per-warp staging tile: [row=lane/session][col=step], padded to 33 float2
    __shared__ float2 tile[MAIN_BLOCK / 32][32][33];
    float2 (*my)[33] = tile[warp];

    // Parameters (uniform; L2/const-cached broadcasts)
    const float a00 = a0[0], a01 = a0[1], a02 = a0[2], a03 = a0[3];
    const float ga0 = ga[0], ga1 = ga[1], ga2 = ga[2], ga3 = ga[3];
    const float gl0 = gl[0], gl1 = gl[1], gl2 = gl[2], gl3 = gl[3];
    const float k0  = kv[0], k1  = kv[1], k2  = kv[2], k3  = kv[3];

    // State
    float QL = 0.0f, QR = 0.0f;
    float lamL = 0.5f, lamR = 0.5f;
    float alpha = 0.0f;

    unsigned cm = g_cmask[tid];
    unsigned om = g_omask[tid];

    for (int w = 0; w < N_TILES; ++w) {
        // prefetch next tile's masks
        unsigned cmn = 0, omn = 0;
        if (w + 1 < N_TILES) {
            cmn = g_cmask[(w + 1) * N_SESS + tid];
            omn = g_omask[(w + 1) * N_SESS + tid];
        }

        #pragma unroll
        for (int i = 0; i < 32; ++i) {
            const bool c = (cm >> i) & 1u;
            const bool o = (om >> i) & 1u;

            // coefficient selects (off critical path; depend only on c,o)
            float u01  = o ? k0  : k1;      // chosen-side k (indices 0/1)
            float u23  = o ? k2  : k3;
            float kL   = c ? u01 : u23;
            float kR   = c ? u23 : u01;
            float gl01 = o ? gl0 : gl1;
            float gl23 = o ? gl2 : gl3;
            float glL  = c ? gl01 : gl23;
            float glR  = c ? gl23 : gl01;
            float gaS  = c ? (o ? ga0 : ga1) : (o ? ga2 : ga3);
            float a0S  = o ? a00 : a01;

            // chosen-side quantities
            float QS   = c ? QL   : QR;
            float lamS = c ? lamL : lamR;
            float dS   = fabsf(u01 - QS);

            // x_a = alpha + gaS*(a0S + dS - lamS - alpha)
            float a1   = fmaf(-gaS, alpha, alpha);          // alpha*(1-gaS)
            float base = fmaf(gaS, a0S - lamS, a1);
            float xa   = fmaf(gaS, dS, base);
            float alpha_new = smooth_clamp01(xa);

            if (w == 0 && i == 0) {
                // t==0: alpha_first = alpha0s[idx_L]
                float af = c ? (o ? a00 : a01) : (o ? a02 : a03);
                alpha_new = af;
            }

            // lambda updates (use OLD Q-side distances)
            float dL = fabsf(kL - QL);
            float dR = fabsf(kR - QR);
            float lamLn = smooth_clamp01(fmaf(glL, dL - lamL, lamL));
            float lamRn = smooth_clamp01(fmaf(glR, dR - lamR, lamR));

            // Q updates (use OLD lambdas, NEW alpha)
            float uL = (1.0f - lamL) * (kL - QL);
            float uR = (1.0f - lamR) * (kR - QR);
            QL = fmaf(alpha_new, uL, QL);
            QR = fmaf(alpha_new, uR, QR);

            alpha = alpha_new;
            lamL  = lamLn;
            lamR  = lamRn;

            my[lane][i] = make_float2(QL, QR);
        }

        __syncwarp();
        // coalesced flush: each lane writes column 'lane' of all 32 session rows
        const int tbase = w * 32;
        #pragma unroll
        for (int r = 0; r < 32; ++r) {
            float2 v = my[r][lane];
            out[(size_t)(sbase + r) * N_TRIALS + tbase + lane] = v;
        }
        __syncwarp();

        cm = cmn;
        om = omn;
    }
}

// ---------------------------------------------------------------------------
extern "C" void kernel_launch(void* const* d_in, const int* in_sizes, int n_in,
                              void* d_out, int out_size)
{
    (void)in_sizes; (void)n_in; (void)out_size;
    const float* input = (const float*)d_in[0];
    const float* a0    = (const float*)d_in[1];
    const float* ga    = (const float*)d_in[2];
    const float* gl    = (const float*)d_in[3];
    const float* kv    = (const float*)d_in[4];
    float2* out = (float2*)d_out;

    // pack: 8192 sessions * 32 tiles = 262144 warps, 8 warps/block
    pack_kernel<<<(N_SESS * N_TILES) / 8, 256>>>(input);

    // main: one thread per session
    agent_kernel<<<N_SESS / MAIN_BLOCK, MAIN_BLOCK>>>(a0, ga, gl, kv, out);
}

// round 2
// speedup vs baseline: 1.0026x; 1.0026x over previous
#include <cuda_runtime.h>
#include <cstdint>

// Problem constants (fixed shapes for this problem)
#define N_SESS   8192
#define N_TRIALS 1024
#define N_TILES  32          // 1024 / 32
#define MAIN_BLOCK 64        // 2 warps/block -> spread over SMs, <=1 warp per SMSP

// Packed masks, time-major: mask[tile*N_SESS + session]
__device__ unsigned g_cmask[N_TILES * N_SESS];
__device__ unsigned g_omask[N_TILES * N_SESS];

// ---------------------------------------------------------------------------
// Pack kernel: input (8192,1024,3) f32 -> 2 bitmasks per (session, 32-trial tile)
// One warp handles 32 consecutive trials of one session via ballot.
// ---------------------------------------------------------------------------
__global__ void pack_kernel(const float* __restrict__ in)
{
    int gtid   = blockIdx.x * blockDim.x + threadIdx.x;
    int warpId = gtid >> 5;            // [0, 8192*32)
    int lane   = gtid & 31;
    int s = warpId >> 5;               // session
    int w = warpId & 31;               // trial tile
    int t = w * 32 + lane;
    const float* p = in + (size_t)s * (N_TRIALS * 3) + (size_t)t * 3;
    float cl = p[0];
    float oc = p[2];
    unsigned mc = __ballot_sync(0xffffffffu, cl > 0.5f);
    unsigned mo = __ballot_sync(0xffffffffu, oc > 0.5f);
    if (lane == 0) {
        g_cmask[w * N_SESS + s] = mc;
        g_omask[w * N_SESS + s] = mo;
    }
}

// smooth_clamp(x, 0, 1), beta = 100.
// sp(z) = softplus(100 z)/100; result = x<0.5 ? sp(x) : 1 - sp(1-x)
// Symmetric: arg a = 0.5 - |x-0.5|. In base-2:
//   w = 144.269504*a ; sp = (max(w,0) + log2(1+2^(-|w|))) * (ln2/100)
__device__ __forceinline__ float smooth_clamp01(float x)
{
    float t = x - 0.5f;
    // w = 144.2695041*(0.5 - |t|)
    float w = fmaf(fabsf(t), -144.26950408889634f, 72.13475204444817f);
    float e = exp2f(-fabsf(w));
    float m = fmaxf(w, 0.0f);
    float l = __log2f(1.0f + e);
    float s = (m + l) * 0.006931471805599453f;
    return (x < 0.5f) ? s : 1.0f - s;
}

// ---------------------------------------------------------------------------
// Main scan kernel: one thread per session, 1024 serial steps.
// Output staged in shared tiles (32 steps) and flushed coalesced.
// ---------------------------------------------------------------------------
__global__ __launch_bounds__(MAIN_BLOCK, 1)
void agent_kernel(const float* __restrict__ a0,
                  const float* __restrict__ ga,
                  const float* __restrict__ gl,
                  const float* __restrict__ kv,
                  float2* __restrict__ out)
{
    const int tid   = blockIdx.x * blockDim.x + threadIdx.x;   // session
    const int lane  = threadIdx.x & 31;
    const int warp  = threadIdx.x >> 5;
    const int sbase = tid - lane;                               // warp's first session

    // per-warp staging tile: [row=lane/session][col=step], padded to 33 float2
    __shared__ float2 tile[MAIN_BLOCK / 32][32][33];
    float2 (*my)[33] = tile[warp];

    // Parameters (uniform; L2/const-cached broadcasts)
    const float a00 = a0[0], a01 = a0[1], a02 = a0[2], a03 = a0[3];
    const float ga0 = ga[0], ga1 = ga[1], ga2 = ga[2], ga3 = ga[3];
    const float gl0 = gl[0], gl1 = gl[1], gl2 = gl[2], gl3 = gl[3];
    const float k0  = kv[0], k1  = kv[1], k2  = kv[2], k3  = kv[3];

    // State
    float QL = 0.0f, QR = 0.0f;
    float lamL = 0.5f, lamR = 0.5f;
    float alpha = 0.0f;

    unsigned cm = g_cmask[tid];
    unsigned om = g_omask[tid];

    for (int w = 0; w < N_TILES; ++w) {
        // prefetch next tile's masks
        unsigned cmn = 0, omn = 0;
        if (w + 1 < N_TILES) {
            cmn = g_cmask[(w + 1) * N_SESS + tid];
            omn = g_omask[(w + 1) * N_SESS + tid];
        }

        #pragma unroll
        for (int i = 0; i < 32; ++i) {
            const bool c = (cm >> i) & 1u;
            const bool o = (om >> i) & 1u;

            // coefficient selects (off critical path; depend only on c,o)
            float u01  = o ? k0  : k1;      // chosen-side k (indices 0/1)
            float u23  = o ? k2  : k3;
            float kL   = c ? u01 : u23;
            float kR   = c ? u23 : u01;
            float gl01 = o ? gl0 : gl1;
            float gl23 = o ? gl2 : gl3;
            float glL  = c ? gl01 : gl23;
            float glR  = c ? gl23 : gl01;
            float gaS  = c ? (o ? ga0 : ga1) : (o ? ga2 : ga3);
            float a0S  = o ? a00 : a01;

            // chosen-side quantities
            float QS   = c ? QL   : QR;
            float lamS = c ? lamL : lamR;
            float dS   = fabsf(u01 - QS);

            // x_a = alpha + gaS*(a0S + dS - lamS - alpha)
            float a1   = fmaf(-gaS, alpha, alpha);          // alpha*(1-gaS)
            float base = fmaf(gaS, a0S - lamS, a1);
            float xa   = fmaf(gaS, dS, base);
            float alpha_new = smooth_clamp01(xa);

            if (w == 0 && i == 0) {
                // t==0: alpha_first = alpha0s[idx_L]
                float af = c ? (o ? a00 : a01) : (o ? a02 : a03);
                alpha_new = af;
            }

            // lambda updates (use OLD Q-side distances)
            float dL = fabsf(kL - QL);
            float dR = fabsf(kR - QR);
            float lamLn = smooth_clamp01(fmaf(glL, dL - lamL, lamL));
            float lamRn = smooth_clamp01(fmaf(glR, dR - lamR, lamR));

            // Q updates (use OLD lambdas, NEW alpha)
            float uL = (1.0f - lamL) * (kL - QL);
            float uR = (1.0f - lamR) * (kR - QR);
            QL = fmaf(alpha_new, uL, QL);
            QR = fmaf(alpha_new, uR, QR);

            alpha = alpha_new;
            lamL  = lamLn;
            lamR  = lamRn;

            my[lane][i] = make_float2(QL, QR);
        }

        __syncwarp();
        // coalesced flush: each lane writes column 'lane' of all 32 session rows
        const int tbase = w * 32;
        #pragma unroll
        for (int r = 0; r < 32; ++r) {
            float2 v = my[r][lane];
            out[(size_t)(sbase + r) * N_TRIALS + tbase + lane] = v;
        }
        __syncwarp();

        cm = cmn;
        om = omn;
    }
}

// ---------------------------------------------------------------------------
extern "C" void kernel_launch(void* const* d_in, const int* in_sizes, int n_in,
                              void* d_out, int out_size)
{
    (void)in_sizes; (void)n_in; (void)out_size;
    const float* input = (const float*)d_in[0];
    const float* a0    = (const float*)d_in[1];
    const float* ga    = (const float*)d_in[2];
    const float* gl    = (const float*)d_in[3];
    const float* kv    = (const float*)d_in[4];
    float2* out = (float2*)d_out;

    // pack: 8192 sessions * 32 tiles = 262144 warps, 8 warps/block
    pack_kernel<<<(N_SESS * N_TILES) / 8, 256>>>(input);

    // main: one thread per session
    agent_kernel<<<N_SESS / MAIN_BLOCK, MAIN_BLOCK>>>(a0, ga, gl, kv, out);
}

// round 4
// speedup vs baseline: 1.4364x; 1.4327x over previous
#include <cuda_runtime.h>
#include <cstdint>

#define N_SESS   8192
#define N_TRIALS 1024
#define N_TILES  32
#define MAIN_BLOCK 64

// Packed masks, time-major: mask[tile*N_SESS + session]
__device__ unsigned g_cmask[N_TILES * N_SESS];
__device__ unsigned g_omask[N_TILES * N_SESS];

// ---------------------------------------------------------------------------
// Pack kernel: fully coalesced. Block = one session (3072 floats = 12 KB).
// Warp w handles 128 trials; lane loads 3 float4 (4 trials, 48 B contiguous).
// Nibbles assembled into 32-bit masks via shared memory.
// ---------------------------------------------------------------------------
__global__ __launch_bounds__(256) void pack_kernel(const float* __restrict__ in)
{
    __shared__ unsigned shc[256], sho[256];
    const int lane = threadIdx.x & 31;
    const int warp = threadIdx.x >> 5;     // 128-trial group, 0..7
    const int s    = blockIdx.x;           // session

    const float4* p = reinterpret_cast<const float4*>(
        in + (size_t)s * 3072 + warp * 384 + lane * 12);
    float4 v0 = p[0], v1 = p[1], v2 = p[2];

    // trial j layout: c at floats {v0.x, v0.w, v1.z, v2.y}, o at {v0.z, v1.y, v2.x, v2.w}
    unsigned nc = (unsigned)(v0.x > 0.5f)        | ((unsigned)(v0.w > 0.5f) << 1)
                | ((unsigned)(v1.z > 0.5f) << 2) | ((unsigned)(v2.y > 0.5f) << 3);
    unsigned no = (unsigned)(v0.z > 0.5f)        | ((unsigned)(v1.y > 0.5f) << 1)
                | ((unsigned)(v2.x > 0.5f) << 2) | ((unsigned)(v2.w > 0.5f) << 3);
    shc[threadIdx.x] = nc;
    sho[threadIdx.x] = no;
    __syncwarp();

    if (lane < 4) {                         // lane = 32-trial subtile within group
        int base = warp * 32 + lane * 8;
        unsigned mc = 0, mo = 0;
        #pragma unroll
        for (int q = 0; q < 8; ++q) {
            mc |= shc[base + q] << (4 * q);
            mo |= sho[base + q] << (4 * q);
        }
        int tileIdx = warp * 4 + lane;
        g_cmask[tileIdx * N_SESS + s] = mc;
        g_omask[tileIdx * N_SESS + s] = mo;
    }
}

// ---------------------------------------------------------------------------
// smooth_clamp(x,0,1), beta=100, fast path:
//   w = 144.2695*(0.5 - |x-0.5|)   (log2-domain softplus argument)
//   sp = max(w,0)*ln2/100 + ln(1+2^(-|w|))/100
// ln(1+e)/100 on e in [0,1] via deg-4 poly (abs err ~1e-6).
// Single MUFU (ex2.approx) per clamp.
// ---------------------------------------------------------------------------
__device__ __forceinline__ float fast_clamp01(float x)
{
    float t  = x - 0.5f;
    float at = __int_as_float(__float_as_int(t) & 0x7fffffff);
    float w  = fmaf(at, -144.26950408889634f, 72.13475204444817f);
    float nw = __int_as_float(__float_as_int(w) | 0x80000000);   // -|w|
    float m  = fmaxf(w, 0.0f);
    float e;
    asm("ex2.approx.f32 %0, %1;" : "=f"(e) : "f"(nw));
    float e2   = e * e;
    float base = fmaf(m, 6.931471805599453e-3f, 1.4882e-6f);     // m*ln2/100 + d0
    float low  = fmaf(9.9627e-3f, e, base);                      // + d1*e
    float hi   = fmaf(-5.5457e-4f, e, 2.1866e-3f);               // d4*e + d3
    hi         = fmaf(hi, e, -4.6644e-3f);                       // *e + d2
    float sp   = fmaf(hi, e2, low);
    return (x < 0.5f) ? sp : 1.0f - sp;
}

// ---------------------------------------------------------------------------
// Main scan: one thread per session, 1024 serial steps.
// Coefficients looked up from a 4-entry shared LUT keyed by code=(c<<1)|o.
// Staging tile padded to 34 float2 columns -> row stride 272 B (16-aligned),
// so the paired-row float4 flush is legal.
// ---------------------------------------------------------------------------
__global__ __launch_bounds__(MAIN_BLOCK, 1)
void agent_kernel(const float* __restrict__ a0p, const float* __restrict__ gap,
                  const float* __restrict__ glp, const float* __restrict__ kvp,
                  float2* __restrict__ out)
{
    __shared__ float4 tab0[4];   // {kL, kR, glL, glR}
    __shared__ float4 tab1[4];   // {gaS, a0S, u01, af}
    __shared__ __align__(16) float2 tile[MAIN_BLOCK / 32][32][34];

    if (threadIdx.x < 4) {
        int code = threadIdx.x;
        int c = code >> 1, o = code & 1;
        float u01  = o ? kvp[0] : kvp[1];
        float u23  = o ? kvp[2] : kvp[3];
        float kL   = c ? u01 : u23;
        float kR   = c ? u23 : u01;
        float gl01 = o ? glp[0] : glp[1];
        float gl23 = o ? glp[2] : glp[3];
        float glL  = c ? gl01 : gl23;
        float glR  = c ? gl23 : gl01;
        float gaS  = c ? (o ? gap[0] : gap[1]) : (o ? gap[2] : gap[3]);
        float a0S  = o ? a0p[0] : a0p[1];
        float af   = c ? (o ? a0p[0] : a0p[1]) : (o ? a0p[2] : a0p[3]);
        tab0[code] = make_float4(kL, kR, glL, glR);
        tab1[code] = make_float4(gaS, a0S, u01, af);
    }
    __syncthreads();

    const int tid   = blockIdx.x * blockDim.x + threadIdx.x;   // session
    const int lane  = threadIdx.x & 31;
    const int warp  = threadIdx.x >> 5;
    const int sbase = tid - lane;
    float2 (*my)[34] = tile[warp];

    float QL = 0.0f, QR = 0.0f;
    float lamL = 0.5f, lamR = 0.5f;
    float alpha = 0.0f;

    unsigned cm = g_cmask[tid];
    unsigned om = g_omask[tid];

    const int half = lane >> 4;          // flush helpers
    const int col  = (lane & 15) << 1;   // even float2 column

    for (int w = 0; w < N_TILES; ++w) {
        unsigned cmn = 0, omn = 0;
        if (w + 1 < N_TILES) {
            cmn = g_cmask[(w + 1) * N_SESS + tid];
            omn = g_omask[(w + 1) * N_SESS + tid];
        }
        const bool firsttile = (w == 0);

        #pragma unroll 16
        for (int i = 0; i < 32; ++i) {
            const unsigned cb = cm & 1u;
            const unsigned ob = om & 1u;
            const bool c = cb;
            const int code = (int)((cb << 1) | ob);
            cm >>= 1; om >>= 1;

            const float4 t0 = tab0[code];   // kL, kR, glL, glR
            const float4 t1 = tab1[code];   // gaS, a0S, u01, af

            // alpha update (critical chain)
            float QS   = c ? QL : QR;
            float lamS = c ? lamL : lamR;
            float dS   = fabsf(t1.z - QS);
            float a1   = fmaf(-t1.x, alpha, alpha);    // alpha*(1-gaS)
            float b2   = fmaf(t1.x, t1.y - lamS, a1);
            float xa   = fmaf(t1.x, dS, b2);
            float alpha_new = fast_clamp01(xa);
            if (firsttile && i == 0) alpha_new = t1.w; // t==0: alpha_first

            // per-side diffs (shared by lambda and Q updates)
            float diffL = t0.x - QL;
            float diffR = t0.y - QR;
            float dL = fabsf(diffL);
            float dR = fabsf(diffR);

            // lambda updates (old Q, old lam)
            float lamLn = fast_clamp01(fmaf(t0.z, dL - lamL, lamL));
            float lamRn = fast_clamp01(fmaf(t0.w, dR - lamR, lamR));

            // Q updates (old lam, new alpha)
            float uL = (1.0f - lamL) * diffL;
            float uR = (1.0f - lamR) * diffR;
            QL = fmaf(alpha_new, uL, QL);
            QR = fmaf(alpha_new, uR, QR);

            alpha = alpha_new;
            lamL  = lamLn;
            lamR  = lamRn;

            my[lane][i] = make_float2(QL, QR);
        }

        __syncwarp();
        // coalesced flush: pair rows, 128-bit LDS + STG
        const int tbase = w * 32;
        #pragma unroll
        for (int r = 0; r < 32; r += 2) {
            int row = r + half;
            float4 v = *reinterpret_cast<const float4*>(&my[row][col]);
            *reinterpret_cast<float4*>(
                &out[(size_t)(sbase + row) * N_TRIALS + tbase + col]) = v;
        }
        __syncwarp();

        cm = cmn;
        om = omn;
    }
}

// ---------------------------------------------------------------------------
extern "C" void kernel_launch(void* const* d_in, const int* in_sizes, int n_in,
                              void* d_out, int out_size)
{
    (void)in_sizes; (void)n_in; (void)out_size;
    const float* input = (const float*)d_in[0];
    const float* a0    = (const float*)d_in[1];
    const float* ga    = (const float*)d_in[2];
    const float* gl    = (const float*)d_in[3];
    const float* kv    = (const float*)d_in[4];
    float2* out = (float2*)d_out;

    pack_kernel<<<N_SESS, 256>>>(input);
    agent_kernel<<<N_SESS / MAIN_BLOCK, MAIN_BLOCK>>>(a0, ga, gl, kv, out);
}